// round 2
// baseline (speedup 1.0000x reference)
#include <cuda_runtime.h>

#define B_ 2
#define S_ 4096
#define D_ 512
#define H_ 8
#define DK_ 64

// Scratch (allocation-free rule: __device__ globals, allocated at module load)
__device__ float g_q[(size_t)B_ * S_ * D_];
__device__ float g_k[(size_t)B_ * S_ * D_];
__device__ float g_v[(size_t)B_ * S_ * D_];
__device__ float g_ctx[(size_t)B_ * S_ * D_];
__device__ float g_attn[(size_t)B_ * H_ * S_ * S_];   // 1.07 GB, [B][H][Sq][Sk]

// ---------------------------------------------------------------------------
// GEMM: C[M,N] = A[M,K] @ W[N,K]^T  (both K-major), optional ReLU.
// 128x128 tile, BK=16, 256 threads, 8x8 per-thread microtile.
// ---------------------------------------------------------------------------
__global__ __launch_bounds__(256) void gemm_nt_kernel(
    const float* __restrict__ A, const float* __restrict__ W,
    float* __restrict__ C, int M, int N, int K, int relu)
{
    __shared__ float As[16][132];
    __shared__ float Bs[16][132];

    const int tid = threadIdx.x;
    const int m0 = blockIdx.y * 128;
    const int n0 = blockIdx.x * 128;
    const int ty = tid >> 4;        // 0..15  -> rows ty*8..
    const int tx = tid & 15;        // 0..15  -> cols tx*8..

    float acc[8][8];
#pragma unroll
    for (int i = 0; i < 8; i++)
#pragma unroll
        for (int j = 0; j < 8; j++) acc[i][j] = 0.0f;

    for (int k0 = 0; k0 < K; k0 += 16) {
#pragma unroll
        for (int t = 0; t < 2; t++) {
            int idx = tid + t * 256;        // 0..511
            int r = idx >> 2;               // 0..127
            int c4 = idx & 3;               // 0..3
            float4 va = *(const float4*)&A[(size_t)(m0 + r) * K + k0 + c4 * 4];
            float4 vb = *(const float4*)&W[(size_t)(n0 + r) * K + k0 + c4 * 4];
            As[c4 * 4 + 0][r] = va.x; As[c4 * 4 + 1][r] = va.y;
            As[c4 * 4 + 2][r] = va.z; As[c4 * 4 + 3][r] = va.w;
            Bs[c4 * 4 + 0][r] = vb.x; Bs[c4 * 4 + 1][r] = vb.y;
            Bs[c4 * 4 + 2][r] = vb.z; Bs[c4 * 4 + 3][r] = vb.w;
        }
        __syncthreads();
#pragma unroll
        for (int kk = 0; kk < 16; kk++) {
            float4 a0 = *(const float4*)&As[kk][ty * 8];
            float4 a1 = *(const float4*)&As[kk][ty * 8 + 4];
            float4 b0 = *(const float4*)&Bs[kk][tx * 8];
            float4 b1 = *(const float4*)&Bs[kk][tx * 8 + 4];
            float a[8] = {a0.x, a0.y, a0.z, a0.w, a1.x, a1.y, a1.z, a1.w};
            float b[8] = {b0.x, b0.y, b0.z, b0.w, b1.x, b1.y, b1.z, b1.w};
#pragma unroll
            for (int i = 0; i < 8; i++)
#pragma unroll
                for (int j = 0; j < 8; j++) acc[i][j] += a[i] * b[j];
        }
        __syncthreads();
    }

#pragma unroll
    for (int i = 0; i < 8; i++) {
        float* crow = &C[(size_t)(m0 + ty * 8 + i) * N + n0 + tx * 8];
        float4 o0, o1;
        if (relu) {
            o0 = make_float4(fmaxf(acc[i][0], 0.f), fmaxf(acc[i][1], 0.f),
                             fmaxf(acc[i][2], 0.f), fmaxf(acc[i][3], 0.f));
            o1 = make_float4(fmaxf(acc[i][4], 0.f), fmaxf(acc[i][5], 0.f),
                             fmaxf(acc[i][6], 0.f), fmaxf(acc[i][7], 0.f));
        } else {
            o0 = make_float4(acc[i][0], acc[i][1], acc[i][2], acc[i][3]);
            o1 = make_float4(acc[i][4], acc[i][5], acc[i][6], acc[i][7]);
        }
        *(float4*)&crow[0] = o0;
        *(float4*)&crow[4] = o1;
    }
}

// ---------------------------------------------------------------------------
// Phase A: scores for all 8 heads of a 64x64 (q,k) tile, kept in registers,
// then softmax over the HEADS axis (reference bug), with the exact fp32
// behavior of adding -1e9 before the /8 scaling for masked (k>q) entries:
//   fl(s - 1e9)/8 == -1.25e8 + 8*rne(s/64)   (ulp(1e9)=64, ties-to-even)
// softmax is shift-invariant, so the effective masked logit is 8*rintf(s/64).
// Writes normalized attention to g_attn[b][h][q][k].
// ---------------------------------------------------------------------------
__global__ __launch_bounds__(256) void scores_softmax_kernel(
    const float* __restrict__ q, const float* __restrict__ k,
    float* __restrict__ attn)
{
    __shared__ float qs[64 * 68];   // [d][q] transposed, pad 68
    __shared__ float ks[64 * 68];   // [d][k]

    const int tid = threadIdx.x;
    const int kt = blockIdx.x;
    const int qt = blockIdx.y;
    const int b  = blockIdx.z;
    const int qy = tid >> 4;        // 0..15 -> q rows qy*4..
    const int kx = tid & 15;        // 0..15 -> k cols kx*4..

    const float* qbase = q + (size_t)(b * S_ + qt * 64) * D_;
    const float* kbase = k + (size_t)(b * S_ + kt * 64) * D_;

    float acc[128];                 // [h][4][4], all-static indexing
#pragma unroll
    for (int i = 0; i < 128; i++) acc[i] = 0.0f;

#pragma unroll
    for (int h = 0; h < 8; h++) {
        __syncthreads();
#pragma unroll
        for (int t = 0; t < 4; t++) {
            int idx = tid + t * 256;     // 0..1023
            int r = idx >> 4;            // 0..63
            int c4 = idx & 15;           // 0..15
            float4 vq = *(const float4*)&qbase[(size_t)r * D_ + h * 64 + c4 * 4];
            float4 vk = *(const float4*)&kbase[(size_t)r * D_ + h * 64 + c4 * 4];
            qs[(c4 * 4 + 0) * 68 + r] = vq.x; qs[(c4 * 4 + 1) * 68 + r] = vq.y;
            qs[(c4 * 4 + 2) * 68 + r] = vq.z; qs[(c4 * 4 + 3) * 68 + r] = vq.w;
            ks[(c4 * 4 + 0) * 68 + r] = vk.x; ks[(c4 * 4 + 1) * 68 + r] = vk.y;
            ks[(c4 * 4 + 2) * 68 + r] = vk.z; ks[(c4 * 4 + 3) * 68 + r] = vk.w;
        }
        __syncthreads();
#pragma unroll 8
        for (int d = 0; d < 64; d++) {
            float4 a4 = *(const float4*)&qs[d * 68 + qy * 4];
            float4 b4 = *(const float4*)&ks[d * 68 + kx * 4];
            float av[4] = {a4.x, a4.y, a4.z, a4.w};
            float bv[4] = {b4.x, b4.y, b4.z, b4.w};
#pragma unroll
            for (int i = 0; i < 4; i++)
#pragma unroll
                for (int j = 0; j < 4; j++)
                    acc[h * 16 + i * 4 + j] += av[i] * bv[j];
        }
    }

    // heads-softmax + write
    const int qg0 = qt * 64 + qy * 4;
    const int kg0 = kt * 64 + kx * 4;
    const size_t bh_stride = (size_t)S_ * S_;

#pragma unroll
    for (int i = 0; i < 4; i++) {
        const int qg = qg0 + i;
        float res[8][4];
#pragma unroll
        for (int j = 0; j < 4; j++) {
            const int kg = kg0 + j;
            const bool masked = (kg > qg);
            float t[8];
#pragma unroll
            for (int h = 0; h < 8; h++) {
                float s = acc[h * 16 + i * 4 + j];
                t[h] = masked ? 8.0f * rintf(s * 0.015625f) : s * 0.125f;
            }
            float m = t[0];
#pragma unroll
            for (int h = 1; h < 8; h++) m = fmaxf(m, t[h]);
            float e[8];
            float sum = 0.0f;
#pragma unroll
            for (int h = 0; h < 8; h++) { e[h] = __expf(t[h] - m); sum += e[h]; }
            float inv = 1.0f / sum;
#pragma unroll
            for (int h = 0; h < 8; h++) res[h][j] = e[h] * inv;
        }
#pragma unroll
        for (int h = 0; h < 8; h++) {
            float4 o = make_float4(res[h][0], res[h][1], res[h][2], res[h][3]);
            *(float4*)&attn[(size_t)(b * 8 + h) * bh_stride + (size_t)qg * S_ + kg0] = o;
        }
    }
}

// ---------------------------------------------------------------------------
// Phase B: ctx[b,q,h*64+d] = sum_k attn[b,h,q,k] * v[b,k,h*64+d]
// Per (b,h): GEMM [4096 x 4096] @ [4096 x 64]. 128x64 tile, BK=32.
// ---------------------------------------------------------------------------
__global__ __launch_bounds__(256) void attn_v_kernel(
    const float* __restrict__ attn, const float* __restrict__ v,
    float* __restrict__ ctx)
{
    __shared__ float As[32 * 132];  // [k][q] transposed
    __shared__ float Vs[32 * 68];   // [k][d]

    const int tid = threadIdx.x;
    const int qt = blockIdx.x;                  // 0..31
    const int bh = blockIdx.y;                  // 0..15
    const int b = bh >> 3, h = bh & 7;

    const float* A = attn + (size_t)bh * S_ * S_ + (size_t)qt * 128 * S_;
    const float* V = v + (size_t)b * S_ * D_ + h * 64;
    float* O = ctx + (size_t)b * S_ * D_ + (size_t)qt * 128 * D_ + h * 64;

    const int ty = tid >> 4;        // rows ty*8..
    const int tx = tid & 15;        // cols tx*4..

    float acc[8][4];
#pragma unroll
    for (int i = 0; i < 8; i++)
#pragma unroll
        for (int j = 0; j < 4; j++) acc[i][j] = 0.0f;

    for (int k0 = 0; k0 < S_; k0 += 32) {
        __syncthreads();
#pragma unroll
        for (int t = 0; t < 4; t++) {
            int idx = tid + t * 256;        // 0..1023
            int r = idx >> 3;               // 0..127 (q row)
            int c4 = idx & 7;               // 0..7   (k /4)
            float4 va = *(const float4*)&A[(size_t)r * S_ + k0 + c4 * 4];
            As[(c4 * 4 + 0) * 132 + r] = va.x;
            As[(c4 * 4 + 1) * 132 + r] = va.y;
            As[(c4 * 4 + 2) * 132 + r] = va.z;
            As[(c4 * 4 + 3) * 132 + r] = va.w;
        }
#pragma unroll
        for (int t = 0; t < 2; t++) {
            int idx = tid + t * 256;        // 0..511
            int r = idx >> 4;               // 0..31  (k row)
            int c4 = idx & 15;              // 0..15  (d /4)
            float4 vv = *(const float4*)&V[(size_t)(k0 + r) * D_ + c4 * 4];
            *(float4*)&Vs[r * 68 + c4 * 4] = vv;
        }
        __syncthreads();
#pragma unroll 8
        for (int kk = 0; kk < 32; kk++) {
            float4 a0 = *(const float4*)&As[kk * 132 + ty * 8];
            float4 a1 = *(const float4*)&As[kk * 132 + ty * 8 + 4];
            float4 b4 = *(const float4*)&Vs[kk * 68 + tx * 4];
            float a[8] = {a0.x, a0.y, a0.z, a0.w, a1.x, a1.y, a1.z, a1.w};
            float bb[4] = {b4.x, b4.y, b4.z, b4.w};
#pragma unroll
            for (int i = 0; i < 8; i++)
#pragma unroll
                for (int j = 0; j < 4; j++) acc[i][j] += a[i] * bb[j];
        }
    }

#pragma unroll
    for (int i = 0; i < 8; i++) {
        float4 o = make_float4(acc[i][0], acc[i][1], acc[i][2], acc[i][3]);
        *(float4*)&O[(size_t)(ty * 8 + i) * D_ + tx * 4] = o;
    }
}

// ---------------------------------------------------------------------------
extern "C" void kernel_launch(void* const* d_in, const int* in_sizes, int n_in,
                              void* d_out, int out_size)
{
    const float* x  = (const float*)d_in[0];
    const float* Wq = (const float*)d_in[1];
    const float* Wk = (const float*)d_in[2];
    const float* Wv = (const float*)d_in[3];
    const float* Wc = (const float*)d_in[4];
    float* out = (float*)d_out;

    float *q, *k, *v, *ctx, *attn;
    cudaGetSymbolAddress((void**)&q, g_q);
    cudaGetSymbolAddress((void**)&k, g_k);
    cudaGetSymbolAddress((void**)&v, g_v);
    cudaGetSymbolAddress((void**)&ctx, g_ctx);
    cudaGetSymbolAddress((void**)&attn, g_attn);

    const int M = B_ * S_;   // 8192
    dim3 gproj(D_ / 128, M / 128);   // (4, 64)

    // Projections
    gemm_nt_kernel<<<gproj, 256>>>(x, Wq, q, M, D_, D_, 0);
    gemm_nt_kernel<<<gproj, 256>>>(x, Wk, k, M, D_, D_, 0);
    gemm_nt_kernel<<<gproj, 256>>>(x, Wv, v, M, D_, D_, 0);

    // Scores + heads-softmax -> attn
    dim3 ga(S_ / 64, S_ / 64, B_);   // (64, 64, 2)
    scores_softmax_kernel<<<ga, 256>>>(q, k, attn);

    // attn @ V -> ctx (combined-head layout)
    dim3 gb(S_ / 128, B_ * H_);      // (32, 16)
    attn_v_kernel<<<gb, 256>>>(attn, v, ctx);

    // Output projection + ReLU
    gemm_nt_kernel<<<gproj, 256>>>(ctx, Wc, out, M, D_, D_, 1);
}

// round 4
// speedup vs baseline: 1.8946x; 1.8946x over previous
#include <cuda_runtime.h>
#include <cuda_bf16.h>

typedef __nv_bfloat16 bf16;
typedef __nv_bfloat162 bf162;

#define B_ 2
#define S_ 4096
#define D_ 512
#define H_ 8
#define M_ (B_ * S_)

// ---------------- scratch ----------------
__device__ bf16 g_xh[(size_t)M_ * D_];
__device__ bf16 g_xl[(size_t)M_ * D_];
__device__ bf16 g_wh[4][D_ * D_];
__device__ bf16 g_wl[4][D_ * D_];
__device__ bf16 g_qh[(size_t)M_ * D_];
__device__ bf16 g_ql[(size_t)M_ * D_];
__device__ bf16 g_kh[(size_t)M_ * D_];
__device__ bf16 g_kl[(size_t)M_ * D_];
__device__ bf16 g_vh[(size_t)M_ * D_];
__device__ bf16 g_vl[(size_t)M_ * D_];
__device__ bf16 g_ch[(size_t)M_ * D_];
__device__ bf16 g_cl[(size_t)M_ * D_];

// ---------------- ptx helpers ----------------
__device__ __forceinline__ unsigned smaddr(const void* p) {
    return (unsigned)__cvta_generic_to_shared(p);
}
__device__ __forceinline__ void ldsm4(unsigned* r, unsigned a) {
    asm volatile("ldmatrix.sync.aligned.m8n8.x4.shared.b16 {%0,%1,%2,%3},[%4];"
                 : "=r"(r[0]), "=r"(r[1]), "=r"(r[2]), "=r"(r[3]) : "r"(a));
}
__device__ __forceinline__ void ldsm2(unsigned* r, unsigned a) {
    asm volatile("ldmatrix.sync.aligned.m8n8.x2.shared.b16 {%0,%1},[%2];"
                 : "=r"(r[0]), "=r"(r[1]) : "r"(a));
}
__device__ __forceinline__ void ldsm2t(unsigned* r, unsigned a) {
    asm volatile("ldmatrix.sync.aligned.m8n8.x2.trans.shared.b16 {%0,%1},[%2];"
                 : "=r"(r[0]), "=r"(r[1]) : "r"(a));
}
__device__ __forceinline__ void mma16816(float* c, const unsigned* a, const unsigned* b) {
    asm volatile(
        "mma.sync.aligned.m16n8k16.row.col.f32.bf16.bf16.f32 "
        "{%0,%1,%2,%3},{%4,%5,%6,%7},{%8,%9},{%0,%1,%2,%3};"
        : "+f"(c[0]), "+f"(c[1]), "+f"(c[2]), "+f"(c[3])
        : "r"(a[0]), "r"(a[1]), "r"(a[2]), "r"(a[3]), "r"(b[0]), "r"(b[1]));
}
__device__ __forceinline__ void cpa16(unsigned d, const void* g) {
    asm volatile("cp.async.cg.shared.global [%0], [%1], 16;" :: "r"(d), "l"(g));
}
__device__ __forceinline__ void cpcommit() { asm volatile("cp.async.commit_group;"); }
__device__ __forceinline__ void cpwait0()  { asm volatile("cp.async.wait_group 0;" ::: "memory"); }

// ---------------- split fp32 -> bf16 hi/lo ----------------
__global__ __launch_bounds__(256) void split_kernel(
    const float* __restrict__ in, bf16* __restrict__ hi, bf16* __restrict__ lo, int n)
{
    int i = blockIdx.x * 256 + threadIdx.x;
    if (i < n) {
        float v = in[i];
        bf16 h = __float2bfloat16(v);
        hi[i] = h;
        lo[i] = __float2bfloat16(v - __bfloat162float(h));
    }
}

// ---------------- projection GEMM: C[M,512] = A[M,512] @ W[512,512]^T --------
// 3-term bf16 mma. mode 0: write bf16 hi/lo. mode 1: relu, write fp32.
__global__ __launch_bounds__(256) void gemm_proj(
    const bf16* __restrict__ Ah, const bf16* __restrict__ Al,
    const bf16* __restrict__ Wh, const bf16* __restrict__ Wl,
    bf16* __restrict__ Ch, bf16* __restrict__ Cl, float* __restrict__ Cf, int mode)
{
    __shared__ bf16 sAh[128 * 40], sAl[128 * 40], sWh[64 * 40], sWl[64 * 40];

    const int tid = threadIdx.x, lane = tid & 31, warp = tid >> 5;
    const int m0 = blockIdx.y * 128, n0 = blockIdx.x * 64;
    const int wm = warp >> 1, wn = warp & 1;

    float acc[2][4][4];
#pragma unroll
    for (int a = 0; a < 2; a++)
#pragma unroll
        for (int b = 0; b < 4; b++)
#pragma unroll
            for (int c = 0; c < 4; c++) acc[a][b][c] = 0.0f;

    for (int k0 = 0; k0 < 512; k0 += 32) {
        __syncthreads();
#pragma unroll
        for (int j = 0; j < 4; j++) {
            int u = tid + j * 256;
            int half = u >> 9, rem = u & 511;
            int row = rem >> 2, c4 = rem & 3;
            const bf16* src = (half ? Al : Ah) + (size_t)(m0 + row) * 512 + k0 + c4 * 8;
            bf16* dst = (half ? sAl : sAh) + row * 40 + c4 * 8;
            *(uint4*)dst = *(const uint4*)src;
        }
#pragma unroll
        for (int j = 0; j < 2; j++) {
            int u = tid + j * 256;
            int half = u >> 8, rem = u & 255;
            int row = rem >> 2, c4 = rem & 3;
            const bf16* src = (half ? Wl : Wh) + (size_t)(n0 + row) * 512 + k0 + c4 * 8;
            bf16* dst = (half ? sWl : sWh) + row * 40 + c4 * 8;
            *(uint4*)dst = *(const uint4*)src;
        }
        __syncthreads();

#pragma unroll
        for (int kc = 0; kc < 2; kc++) {
            unsigned ah[2][4], al[2][4];
#pragma unroll
            for (int mi = 0; mi < 2; mi++) {
                int r = wm * 32 + mi * 16 + (lane & 15);
                int cc = kc * 16 + (lane >> 4) * 8;
                ldsm4(ah[mi], smaddr(&sAh[r * 40 + cc]));
                ldsm4(al[mi], smaddr(&sAl[r * 40 + cc]));
            }
#pragma unroll
            for (int ni = 0; ni < 4; ni++) {
                int r = wn * 32 + ni * 8 + (lane & 7);
                int cc = kc * 16 + ((lane >> 3) & 1) * 8;
                unsigned bh[2], bl[2];
                ldsm2(bh, smaddr(&sWh[r * 40 + cc]));
                ldsm2(bl, smaddr(&sWl[r * 40 + cc]));
#pragma unroll
                for (int mi = 0; mi < 2; mi++) {
                    mma16816(acc[mi][ni], ah[mi], bh);
                    mma16816(acc[mi][ni], ah[mi], bl);
                    mma16816(acc[mi][ni], al[mi], bh);
                }
            }
        }
    }

#pragma unroll
    for (int mi = 0; mi < 2; mi++)
#pragma unroll
        for (int ni = 0; ni < 4; ni++) {
#pragma unroll
            for (int half = 0; half < 2; half++) {
                int row = m0 + wm * 32 + mi * 16 + (lane >> 2) + half * 8;
                int col = n0 + wn * 32 + ni * 8 + (lane & 3) * 2;
                float v0 = acc[mi][ni][half * 2 + 0];
                float v1 = acc[mi][ni][half * 2 + 1];
                size_t off = (size_t)row * 512 + col;
                if (mode == 1) {
                    float2 o = make_float2(fmaxf(v0, 0.f), fmaxf(v1, 0.f));
                    *(float2*)&Cf[off] = o;
                } else {
                    bf16 h0 = __float2bfloat16(v0), h1 = __float2bfloat16(v1);
                    bf16 l0 = __float2bfloat16(v0 - __bfloat162float(h0));
                    bf16 l1 = __float2bfloat16(v1 - __bfloat162float(h1));
                    *(bf162*)&Ch[off] = bf162(h0, h1);
                    *(bf162*)&Cl[off] = bf162(l0, l1);
                }
            }
        }
}

// ---------------- fused attention -----------------------------------------
// Per CTA: 32 q rows, all 8 heads (warp h = head h), loop k in tiles of 16.
//   scores (bf16 3-term mma) -> smem -> heads-softmax (rintf -1e9 emulation)
//   -> attn bf16 hi/lo -> attn@V mma -> ctx accumulators -> hi/lo epilogue.
#define KVB 33280           // bf16 elems per KV double buffer half
#define SCST 544            // 32*17 floats per head
#define ATST 768            // 32*24 bf16 per head

__global__ __launch_bounds__(256, 1) void fused_attn(
    const bf16* __restrict__ qh, const bf16* __restrict__ ql,
    const bf16* __restrict__ kh, const bf16* __restrict__ kl,
    const bf16* __restrict__ vh, const bf16* __restrict__ vl)
{
    extern __shared__ char smem[];
    bf16* kv = (bf16*)smem;                              // 2 * 33280 bf16
    float* ssc = (float*)(smem + 133120);                // 8*544 floats
    bf16* sath = (bf16*)(smem + 150528);                 // 8*768 bf16
    bf16* satl = (bf16*)(smem + 162816);                 // 8*768 bf16

    const int tid = threadIdx.x, lane = tid & 31, h = tid >> 5;
    const int qt = blockIdx.x, b = blockIdx.y;
    const size_t kvbase = (size_t)b * S_ * D_;

    // ---- stage Q (32x512 hi/lo): 2 halves x 32 rows x 64 chunks = 4096 ----
    {
        bf16* qsh = kv;            // 16384 elems
        bf16* qsl = kv + 16384;
#pragma unroll
        for (int j = 0; j < 16; j++) {
            int u = tid + j * 256;             // 0..4095
            int half = u >> 11, rem = u & 2047;
            int row = rem >> 6, c8 = rem & 63;
            const bf16* src = (half ? ql : qh) +
                (size_t)(b * S_ + qt * 32 + row) * 512 + c8 * 8;
            bf16* dst = (half ? qsl : qsh) + row * 512 + c8 * 8;
            *(uint4*)dst = *(const uint4*)src;
        }
        __syncthreads();
    }
    unsigned qfh[2][4][4], qfl[2][4][4];
#pragma unroll
    for (int mi = 0; mi < 2; mi++)
#pragma unroll
        for (int dc = 0; dc < 4; dc++) {
            int row = mi * 16 + (lane & 15);
            int col = h * 64 + dc * 16 + (lane >> 4) * 8;
            ldsm4(qfh[mi][dc], smaddr(&kv[row * 512 + col]));
            ldsm4(qfl[mi][dc], smaddr(&kv[16384 + row * 512 + col]));
        }
    __syncthreads();   // buffer 0 free for KV now

    float cacc[2][8][4];
#pragma unroll
    for (int mi = 0; mi < 2; mi++)
#pragma unroll
        for (int ni = 0; ni < 8; ni++)
#pragma unroll
            for (int c = 0; c < 4; c++) cacc[mi][ni][c] = 0.0f;

    // ---- prefetch iter 0 into buf 0: 4 arrays x 16 rows x 64 chunks ----
    {
        bf16* buf = kv;
#pragma unroll
        for (int j = 0; j < 16; j++) {
            int c = tid + j * 256;             // 0..4095
            int arr = c >> 10, rem = c & 1023;
            int r = rem >> 6, cc = rem & 63;
            const bf16* base = (arr == 0) ? kh : (arr == 1) ? kl : (arr == 2) ? vh : vl;
            const bf16* src = base + kvbase + (size_t)r * 512 + cc * 8;
            cpa16(smaddr(buf + arr * 8320 + r * 520 + cc * 8), src);
        }
        cpcommit();
    }

    const int qg0 = qt * 32;

    for (int it = 0; it < 256; it++) {
        bf16* buf = kv + (it & 1) * KVB;
        const bf16* Khi = buf;
        const bf16* Vhi = buf + 16640;
        const bf16* Vlo = buf + 24960;

        cpwait0();
        __syncthreads();   // KV[it] ready; prev iter's reads all done

        if (it + 1 < 256) {
            bf16* nb = kv + ((it + 1) & 1) * KVB;
            const size_t rowoff = kvbase + (size_t)(it + 1) * 16 * 512;
#pragma unroll
            for (int j = 0; j < 16; j++) {
                int c = tid + j * 256;
                int arr = c >> 10, rem = c & 1023;
                int r = rem >> 6, cc = rem & 63;
                const bf16* base = (arr == 0) ? kh : (arr == 1) ? kl : (arr == 2) ? vh : vl;
                const bf16* src = base + rowoff + (size_t)r * 512 + cc * 8;
                cpa16(smaddr(nb + arr * 8320 + r * 520 + cc * 8), src);
            }
            cpcommit();
        }

        // ---- scores: S[32q][16k] for head h ----
        float cs[2][2][4];
#pragma unroll
        for (int mi = 0; mi < 2; mi++)
#pragma unroll
            for (int ni = 0; ni < 2; ni++)
#pragma unroll
                for (int c = 0; c < 4; c++) cs[mi][ni][c] = 0.0f;

#pragma unroll
        for (int dc = 0; dc < 4; dc++) {
#pragma unroll
            for (int ni = 0; ni < 2; ni++) {
                int kr = ni * 8 + (lane & 7);
                int col = h * 64 + dc * 16 + ((lane >> 3) & 1) * 8;
                unsigned bh2[2], bl2[2];
                ldsm2(bh2, smaddr(&Khi[kr * 520 + col]));
                ldsm2(bl2, smaddr(&Khi[8320 + kr * 520 + col]));
#pragma unroll
                for (int mi = 0; mi < 2; mi++) {
                    mma16816(cs[mi][ni], qfh[mi][dc], bh2);
                    mma16816(cs[mi][ni], qfh[mi][dc], bl2);
                    mma16816(cs[mi][ni], qfl[mi][dc], bh2);
                }
            }
        }
#pragma unroll
        for (int mi = 0; mi < 2; mi++)
#pragma unroll
            for (int ni = 0; ni < 2; ni++) {
                int row = mi * 16 + (lane >> 2);
                int col = ni * 8 + (lane & 3) * 2;
                ssc[h * SCST + row * 17 + col]       = cs[mi][ni][0];
                ssc[h * SCST + row * 17 + col + 1]   = cs[mi][ni][1];
                ssc[h * SCST + (row + 8) * 17 + col]     = cs[mi][ni][2];
                ssc[h * SCST + (row + 8) * 17 + col + 1] = cs[mi][ni][3];
            }
        __syncthreads();

        // ---- heads softmax: 512 (q,k) pairs, 2 per thread ----
#pragma unroll
        for (int rep = 0; rep < 2; rep++) {
            int p = tid + rep * 256;
            int q = p >> 4, kk = p & 15;
            int qg = qg0 + q, kg = it * 16 + kk;
            bool masked = kg > qg;
            float t[8];
#pragma unroll
            for (int hh = 0; hh < 8; hh++) {
                float s = ssc[hh * SCST + q * 17 + kk];
                t[hh] = masked ? 8.0f * rintf(s * 0.015625f) : s * 0.125f;
            }
            float m = t[0];
#pragma unroll
            for (int hh = 1; hh < 8; hh++) m = fmaxf(m, t[hh]);
            float e[8], sum = 0.0f;
#pragma unroll
            for (int hh = 0; hh < 8; hh++) { e[hh] = __expf(t[hh] - m); sum += e[hh]; }
            float inv = 1.0f / sum;
#pragma unroll
            for (int hh = 0; hh < 8; hh++) {
                float a = e[hh] * inv;
                bf16 ah = __float2bfloat16(a);
                sath[hh * ATST + q * 24 + kk] = ah;
                satl[hh * ATST + q * 24 + kk] =
                    __float2bfloat16(a - __bfloat162float(ah));
            }
        }
        __syncthreads();

        // ---- attn @ V ----
        unsigned aah[2][4], aal[2][4];
#pragma unroll
        for (int mi = 0; mi < 2; mi++) {
            int row = mi * 16 + (lane & 15);
            int cc = (lane >> 4) * 8;
            ldsm4(aah[mi], smaddr(&sath[h * ATST + row * 24 + cc]));
            ldsm4(aal[mi], smaddr(&satl[h * ATST + row * 24 + cc]));
        }
#pragma unroll
        for (int ni = 0; ni < 8; ni++) {
            int col = h * 64 + ni * 8;
            unsigned bvh[2], bvl[2];
            ldsm2t(bvh, smaddr(&Vhi[(lane & 15) * 520 + col]));
            ldsm2t(bvl, smaddr(&Vlo[(lane & 15) * 520 + col]));
#pragma unroll
            for (int mi = 0; mi < 2; mi++) {
                mma16816(cacc[mi][ni], aah[mi], bvh);
                mma16816(cacc[mi][ni], aah[mi], bvl);
                mma16816(cacc[mi][ni], aal[mi], bvh);
            }
        }
    }

    // ---- epilogue: ctx -> bf16 hi/lo ----
#pragma unroll
    for (int mi = 0; mi < 2; mi++)
#pragma unroll
        for (int ni = 0; ni < 8; ni++)
#pragma unroll
            for (int half = 0; half < 2; half++) {
                int row = b * S_ + qg0 + mi * 16 + (lane >> 2) + half * 8;
                int col = h * 64 + ni * 8 + (lane & 3) * 2;
                float v0 = cacc[mi][ni][half * 2 + 0];
                float v1 = cacc[mi][ni][half * 2 + 1];
                bf16 h0 = __float2bfloat16(v0), h1 = __float2bfloat16(v1);
                bf16 l0 = __float2bfloat16(v0 - __bfloat162float(h0));
                bf16 l1 = __float2bfloat16(v1 - __bfloat162float(h1));
                size_t off = (size_t)row * 512 + col;
                *(bf162*)&g_ch[off] = bf162(h0, h1);
                *(bf162*)&g_cl[off] = bf162(l0, l1);
            }
}

// ---------------------------------------------------------------------------
extern "C" void kernel_launch(void* const* d_in, const int* in_sizes, int n_in,
                              void* d_out, int out_size)
{
    const float* x  = (const float*)d_in[0];
    const float* W[4] = {(const float*)d_in[1], (const float*)d_in[2],
                         (const float*)d_in[3], (const float*)d_in[4]};
    float* out = (float*)d_out;

    bf16 *xh, *xl, *wh, *wl, *qh, *ql, *kh, *kl, *vh, *vl, *ch, *cl;
    cudaGetSymbolAddress((void**)&xh, g_xh);
    cudaGetSymbolAddress((void**)&xl, g_xl);
    cudaGetSymbolAddress((void**)&wh, g_wh);
    cudaGetSymbolAddress((void**)&wl, g_wl);
    cudaGetSymbolAddress((void**)&qh, g_qh);
    cudaGetSymbolAddress((void**)&ql, g_ql);
    cudaGetSymbolAddress((void**)&kh, g_kh);
    cudaGetSymbolAddress((void**)&kl, g_kl);
    cudaGetSymbolAddress((void**)&vh, g_vh);
    cudaGetSymbolAddress((void**)&vl, g_vl);
    cudaGetSymbolAddress((void**)&ch, g_ch);
    cudaGetSymbolAddress((void**)&cl, g_cl);

    // splits
    split_kernel<<<(M_ * D_) / 256, 256>>>(x, xh, xl, M_ * D_);
    for (int i = 0; i < 4; i++)
        split_kernel<<<(D_ * D_) / 256, 256>>>(W[i], wh + (size_t)i * D_ * D_,
                                               wl + (size_t)i * D_ * D_, D_ * D_);

    dim3 gp(D_ / 64, M_ / 128);   // (8, 64)
    gemm_proj<<<gp, 256>>>(xh, xl, wh, wl, qh, ql, nullptr, 0);
    gemm_proj<<<gp, 256>>>(xh, xl, wh + (size_t)1 * D_ * D_, wl + (size_t)1 * D_ * D_,
                           kh, kl, nullptr, 0);
    gemm_proj<<<gp, 256>>>(xh, xl, wh + (size_t)2 * D_ * D_, wl + (size_t)2 * D_ * D_,
                           vh, vl, nullptr, 0);

    cudaFuncSetAttribute(fused_attn, cudaFuncAttributeMaxDynamicSharedMemorySize,
                         175104);
    dim3 ga(S_ / 32, B_);         // (128, 2)
    fused_attn<<<ga, 256, 175104>>>(qh, ql, kh, kl, vh, vl);

    gemm_proj<<<gp, 256>>>(ch, cl, wh + (size_t)3 * D_ * D_, wl + (size_t)3 * D_ * D_,
                           nullptr, nullptr, out, 1);
}

// round 5
// speedup vs baseline: 2.7232x; 1.4373x over previous
#include <cuda_runtime.h>
#include <cuda_bf16.h>
#include <cuda_fp16.h>

typedef __nv_bfloat16 bf16;
typedef __nv_bfloat162 bf162;

#define B_ 2
#define S_ 4096
#define D_ 512
#define M_ (B_ * S_)

// ---------------- scratch ----------------
__device__ bf16 g_xh[(size_t)M_ * D_];
__device__ bf16 g_xl[(size_t)M_ * D_];
__device__ bf16 g_wh[4][D_ * D_];
__device__ bf16 g_wl[4][D_ * D_];
__device__ bf16 g_qh[(size_t)M_ * D_];
__device__ bf16 g_ql[(size_t)M_ * D_];
__device__ bf16 g_kh[(size_t)M_ * D_];
__device__ bf16 g_kl[(size_t)M_ * D_];
__device__ __half g_vf[(size_t)M_ * D_];
__device__ bf16 g_ch[(size_t)M_ * D_];
__device__ bf16 g_cl[(size_t)M_ * D_];

// ---------------- ptx helpers ----------------
__device__ __forceinline__ unsigned smaddr(const void* p) {
    return (unsigned)__cvta_generic_to_shared(p);
}
__device__ __forceinline__ void ldsm4(unsigned* r, unsigned a) {
    asm volatile("ldmatrix.sync.aligned.m8n8.x4.shared.b16 {%0,%1,%2,%3},[%4];"
                 : "=r"(r[0]), "=r"(r[1]), "=r"(r[2]), "=r"(r[3]) : "r"(a));
}
__device__ __forceinline__ void ldsm2(unsigned* r, unsigned a) {
    asm volatile("ldmatrix.sync.aligned.m8n8.x2.shared.b16 {%0,%1},[%2];"
                 : "=r"(r[0]), "=r"(r[1]) : "r"(a));
}
__device__ __forceinline__ void ldsm2t(unsigned* r, unsigned a) {
    asm volatile("ldmatrix.sync.aligned.m8n8.x2.trans.shared.b16 {%0,%1},[%2];"
                 : "=r"(r[0]), "=r"(r[1]) : "r"(a));
}
__device__ __forceinline__ void mma16816(float* c, const unsigned* a, const unsigned* b) {
    asm volatile(
        "mma.sync.aligned.m16n8k16.row.col.f32.bf16.bf16.f32 "
        "{%0,%1,%2,%3},{%4,%5,%6,%7},{%8,%9},{%0,%1,%2,%3};"
        : "+f"(c[0]), "+f"(c[1]), "+f"(c[2]), "+f"(c[3])
        : "r"(a[0]), "r"(a[1]), "r"(a[2]), "r"(a[3]), "r"(b[0]), "r"(b[1]));
}
__device__ __forceinline__ void mma16816h(float* c, const unsigned* a, const unsigned* b) {
    asm volatile(
        "mma.sync.aligned.m16n8k16.row.col.f32.f16.f16.f32 "
        "{%0,%1,%2,%3},{%4,%5,%6,%7},{%8,%9},{%0,%1,%2,%3};"
        : "+f"(c[0]), "+f"(c[1]), "+f"(c[2]), "+f"(c[3])
        : "r"(a[0]), "r"(a[1]), "r"(a[2]), "r"(a[3]), "r"(b[0]), "r"(b[1]));
}
__device__ __forceinline__ void cpa16(unsigned d, const void* g) {
    asm volatile("cp.async.cg.shared.global [%0], [%1], 16;" :: "r"(d), "l"(g));
}
__device__ __forceinline__ void cpcommit() { asm volatile("cp.async.commit_group;"); }
__device__ __forceinline__ void cpwait0()  { asm volatile("cp.async.wait_group 0;" ::: "memory"); }

// ---------------- split fp32 -> bf16 hi/lo ----------------
__global__ __launch_bounds__(256) void split_kernel(
    const float* __restrict__ in, bf16* __restrict__ hi, bf16* __restrict__ lo, int n)
{
    int i = blockIdx.x * 256 + threadIdx.x;
    if (i < n) {
        float v = in[i];
        bf16 h = __float2bfloat16(v);
        hi[i] = h;
        lo[i] = __float2bfloat16(v - __bfloat162float(h));
    }
}

// ---------------- projection GEMM: C[M,512] = A[M,512] @ W[512,512]^T --------
// 3-term bf16 mma. mode 0: bf16 hi/lo out. mode 1: relu + fp32 out. mode 2: fp16 out.
__global__ __launch_bounds__(256) void gemm_proj(
    const bf16* __restrict__ Ah, const bf16* __restrict__ Al,
    const bf16* __restrict__ Wh, const bf16* __restrict__ Wl,
    bf16* __restrict__ Ch, bf16* __restrict__ Cl,
    float* __restrict__ Cf, __half* __restrict__ Cfh, int mode)
{
    __shared__ bf16 sAh[128 * 40], sAl[128 * 40], sWh[64 * 40], sWl[64 * 40];

    const int tid = threadIdx.x, lane = tid & 31, warp = tid >> 5;
    const int m0 = blockIdx.y * 128, n0 = blockIdx.x * 64;
    const int wm = warp >> 1, wn = warp & 1;

    float acc[2][4][4];
#pragma unroll
    for (int a = 0; a < 2; a++)
#pragma unroll
        for (int b = 0; b < 4; b++)
#pragma unroll
            for (int c = 0; c < 4; c++) acc[a][b][c] = 0.0f;

    for (int k0 = 0; k0 < 512; k0 += 32) {
        __syncthreads();
#pragma unroll
        for (int j = 0; j < 4; j++) {
            int u = tid + j * 256;
            int half = u >> 9, rem = u & 511;
            int row = rem >> 2, c4 = rem & 3;
            const bf16* src = (half ? Al : Ah) + (size_t)(m0 + row) * 512 + k0 + c4 * 8;
            bf16* dst = (half ? sAl : sAh) + row * 40 + c4 * 8;
            *(uint4*)dst = *(const uint4*)src;
        }
#pragma unroll
        for (int j = 0; j < 2; j++) {
            int u = tid + j * 256;
            int half = u >> 8, rem = u & 255;
            int row = rem >> 2, c4 = rem & 3;
            const bf16* src = (half ? Wl : Wh) + (size_t)(n0 + row) * 512 + k0 + c4 * 8;
            bf16* dst = (half ? sWl : sWh) + row * 40 + c4 * 8;
            *(uint4*)dst = *(const uint4*)src;
        }
        __syncthreads();

#pragma unroll
        for (int kc = 0; kc < 2; kc++) {
            unsigned ah[2][4], al[2][4];
#pragma unroll
            for (int mi = 0; mi < 2; mi++) {
                int r = wm * 32 + mi * 16 + (lane & 15);
                int cc = kc * 16 + (lane >> 4) * 8;
                ldsm4(ah[mi], smaddr(&sAh[r * 40 + cc]));
                ldsm4(al[mi], smaddr(&sAl[r * 40 + cc]));
            }
#pragma unroll
            for (int ni = 0; ni < 4; ni++) {
                int r = wn * 32 + ni * 8 + (lane & 7);
                int cc = kc * 16 + ((lane >> 3) & 1) * 8;
                unsigned bh[2], bl[2];
                ldsm2(bh, smaddr(&sWh[r * 40 + cc]));
                ldsm2(bl, smaddr(&sWl[r * 40 + cc]));
#pragma unroll
                for (int mi = 0; mi < 2; mi++) {
                    mma16816(acc[mi][ni], ah[mi], bh);
                    mma16816(acc[mi][ni], ah[mi], bl);
                    mma16816(acc[mi][ni], al[mi], bh);
                }
            }
        }
    }

#pragma unroll
    for (int mi = 0; mi < 2; mi++)
#pragma unroll
        for (int ni = 0; ni < 4; ni++) {
#pragma unroll
            for (int half = 0; half < 2; half++) {
                int row = m0 + wm * 32 + mi * 16 + (lane >> 2) + half * 8;
                int col = n0 + wn * 32 + ni * 8 + (lane & 3) * 2;
                float v0 = acc[mi][ni][half * 2 + 0];
                float v1 = acc[mi][ni][half * 2 + 1];
                size_t off = (size_t)row * 512 + col;
                if (mode == 1) {
                    *(float2*)&Cf[off] = make_float2(fmaxf(v0, 0.f), fmaxf(v1, 0.f));
                } else if (mode == 2) {
                    *(__half2*)&Cfh[off] = __floats2half2_rn(v0, v1);
                } else {
                    bf16 h0 = __float2bfloat16(v0), h1 = __float2bfloat16(v1);
                    bf16 l0 = __float2bfloat16(v0 - __bfloat162float(h0));
                    bf16 l1 = __float2bfloat16(v1 - __bfloat162float(h1));
                    *(bf162*)&Ch[off] = bf162(h0, h1);
                    *(bf162*)&Cl[off] = bf162(l0, l1);
                }
            }
        }
}

// ---------------- fused attention -----------------------------------------
// CTA: 64 q rows x all heads, 512 threads. warp = (head, q-half of 32 rows).
// scores: 3-term bf16 mma (Q-hi frags in regs, Q-lo re-ldsm from smem).
// heads-softmax (rintf -1e9 emulation) -> attn fp16 -> PV single fp16 mma.
#define QSTR 520
#define KVELEM 24960        // elems per KV buffer (Khi/Klo bf16 + V fp16, 16x520 each)
#define SCH 1088            // floats per head in ssc (64*17)
#define ATH 1536            // halfs per head in sat (64*24)

__global__ __launch_bounds__(512, 1) void fused_attn(
    const bf16* __restrict__ qhp, const bf16* __restrict__ qlp,
    const bf16* __restrict__ khp, const bf16* __restrict__ klp,
    const __half* __restrict__ vfp)
{
    extern __shared__ char smem[];
    bf16* sql = (bf16*)smem;                       // 64x520 bf16 = 66560 B (persistent)
    bf16* kv  = (bf16*)(smem + 66560);             // 2 x 24960 elems = 99840 B
    float* ssc = (float*)(smem + 166400);          // 8 x 1088 fp32 = 34816 B
    __half* sat = (__half*)(smem + 201216);        // 8 x 1536 fp16 = 24576 B

    const int tid = threadIdx.x, lane = tid & 31, w = tid >> 5;
    const int h = w & 7, qhalf = w >> 3;
    const int qt = blockIdx.x, b = blockIdx.y;
    const size_t kvbase = (size_t)b * S_ * D_;
    const int qg0 = qt * 64;

    // ---- stage Q: hi -> kv area (transient), lo -> sql (persistent) ----
#pragma unroll
    for (int j = 0; j < 16; j++) {
        int u = tid + j * 512;                 // 0..8191
        int hs = u >> 12, rem = u & 4095;
        int row = rem >> 6, cc = rem & 63;
        const bf16* src = (hs ? qlp : qhp) + (size_t)(b * S_ + qg0 + row) * 512 + cc * 8;
        bf16* dst = (hs ? sql : kv) + row * QSTR + cc * 8;
        *(uint4*)dst = *(const uint4*)src;
    }
    __syncthreads();

    unsigned qfh[2][4][4];
#pragma unroll
    for (int mi = 0; mi < 2; mi++)
#pragma unroll
        for (int dc = 0; dc < 4; dc++) {
            int row = qhalf * 32 + mi * 16 + (lane & 15);
            int col = h * 64 + dc * 16 + (lane >> 4) * 8;
            ldsm4(qfh[mi][dc], smaddr(&kv[row * QSTR + col]));
        }
    __syncthreads();    // kv area free for KV streaming

    float cacc[2][8][4];
#pragma unroll
    for (int mi = 0; mi < 2; mi++)
#pragma unroll
        for (int ni = 0; ni < 8; ni++)
#pragma unroll
            for (int c = 0; c < 4; c++) cacc[mi][ni][c] = 0.0f;

    // ---- prefetch iter 0: 3 arrays x 16 rows x 64 chunks = 3072 ----
#pragma unroll
    for (int j = 0; j < 6; j++) {
        int c = tid + j * 512;
        int arr = c >> 10, rem = c & 1023;
        int r = rem >> 6, cc = rem & 63;
        size_t goff = kvbase + (size_t)r * 512 + cc * 8;
        const void* src = (arr == 0) ? (const void*)(khp + goff)
                        : (arr == 1) ? (const void*)(klp + goff)
                                     : (const void*)(vfp + goff);
        cpa16(smaddr(kv + arr * 8320 + r * 520 + cc * 8), src);
    }
    cpcommit();

    for (int it = 0; it < 256; it++) {
        bf16* buf = kv + (it & 1) * KVELEM;
        const bf16* Khi = buf;
        const bf16* Klo = buf + 8320;
        const __half* Vf = (const __half*)(buf + 16640);

        cpwait0();
        __syncthreads();

        if (it + 1 < 256) {
            bf16* nb = kv + ((it + 1) & 1) * KVELEM;
            const size_t rowoff = kvbase + (size_t)(it + 1) * 16 * 512;
#pragma unroll
            for (int j = 0; j < 6; j++) {
                int c = tid + j * 512;
                int arr = c >> 10, rem = c & 1023;
                int r = rem >> 6, cc = rem & 63;
                size_t goff = rowoff + (size_t)r * 512 + cc * 8;
                const void* src = (arr == 0) ? (const void*)(khp + goff)
                                : (arr == 1) ? (const void*)(klp + goff)
                                             : (const void*)(vfp + goff);
                cpa16(smaddr(nb + arr * 8320 + r * 520 + cc * 8), src);
            }
            cpcommit();
        }

        // ---- scores: 32q x 16k for (head h, half) ----
        float cs[2][2][4];
#pragma unroll
        for (int mi = 0; mi < 2; mi++)
#pragma unroll
            for (int ni = 0; ni < 2; ni++)
#pragma unroll
                for (int c = 0; c < 4; c++) cs[mi][ni][c] = 0.0f;

#pragma unroll
        for (int dc = 0; dc < 4; dc++) {
            unsigned kh2[2][2], kl2[2][2];
#pragma unroll
            for (int ni = 0; ni < 2; ni++) {
                int kr = ni * 8 + (lane & 7);
                int col = h * 64 + dc * 16 + ((lane >> 3) & 1) * 8;
                ldsm2(kh2[ni], smaddr(&Khi[kr * 520 + col]));
                ldsm2(kl2[ni], smaddr(&Klo[kr * 520 + col]));
            }
#pragma unroll
            for (int mi = 0; mi < 2; mi++) {
                unsigned qlf[4];
                int row = qhalf * 32 + mi * 16 + (lane & 15);
                int col = h * 64 + dc * 16 + (lane >> 4) * 8;
                ldsm4(qlf, smaddr(&sql[row * QSTR + col]));
#pragma unroll
                for (int ni = 0; ni < 2; ni++) {
                    mma16816(cs[mi][ni], qfh[mi][dc], kh2[ni]);
                    mma16816(cs[mi][ni], qfh[mi][dc], kl2[ni]);
                    mma16816(cs[mi][ni], qlf, kh2[ni]);
                }
            }
        }
#pragma unroll
        for (int mi = 0; mi < 2; mi++)
#pragma unroll
            for (int ni = 0; ni < 2; ni++) {
                int row = qhalf * 32 + mi * 16 + (lane >> 2);
                int col = ni * 8 + (lane & 3) * 2;
                float* p0 = &ssc[h * SCH + row * 17 + col];
                p0[0] = cs[mi][ni][0]; p0[1] = cs[mi][ni][1];
                float* p1 = &ssc[h * SCH + (row + 8) * 17 + col];
                p1[0] = cs[mi][ni][2]; p1[1] = cs[mi][ni][3];
            }
        __syncthreads();

        // ---- heads softmax: 1024 (q,k) pairs, 2 per thread ----
#pragma unroll
        for (int rep = 0; rep < 2; rep++) {
            int p = tid + rep * 512;
            int q = p >> 4, kk = p & 15;
            int qg = qg0 + q, kg = it * 16 + kk;
            bool masked = kg > qg;
            float t[8];
#pragma unroll
            for (int hh = 0; hh < 8; hh++) {
                float s = ssc[hh * SCH + q * 17 + kk];
                t[hh] = masked ? 8.0f * rintf(s * 0.015625f) : s * 0.125f;
            }
            float m = t[0];
#pragma unroll
            for (int hh = 1; hh < 8; hh++) m = fmaxf(m, t[hh]);
            float e[8], sum = 0.0f;
#pragma unroll
            for (int hh = 0; hh < 8; hh++) { e[hh] = __expf(t[hh] - m); sum += e[hh]; }
            float inv = 1.0f / sum;
#pragma unroll
            for (int hh = 0; hh < 8; hh++)
                sat[hh * ATH + q * 24 + kk] = __float2half_rn(e[hh] * inv);
        }
        __syncthreads();

        // ---- PV: single fp16 mma ----
        unsigned af[2][4];
#pragma unroll
        for (int mi = 0; mi < 2; mi++) {
            int row = qhalf * 32 + mi * 16 + (lane & 15);
            ldsm4(af[mi], smaddr(&sat[h * ATH + row * 24 + (lane >> 4) * 8]));
        }
#pragma unroll
        for (int ni = 0; ni < 8; ni++) {
            unsigned v2[2];
            ldsm2t(v2, smaddr(&Vf[(lane & 15) * 520 + h * 64 + ni * 8]));
#pragma unroll
            for (int mi = 0; mi < 2; mi++)
                mma16816h(cacc[mi][ni], af[mi], v2);
        }
    }

    // ---- epilogue: ctx -> bf16 hi/lo ----
#pragma unroll
    for (int mi = 0; mi < 2; mi++)
#pragma unroll
        for (int ni = 0; ni < 8; ni++)
#pragma unroll
            for (int hf = 0; hf < 2; hf++) {
                int row = b * S_ + qg0 + qhalf * 32 + mi * 16 + (lane >> 2) + hf * 8;
                int col = h * 64 + ni * 8 + (lane & 3) * 2;
                float v0 = cacc[mi][ni][hf * 2 + 0];
                float v1 = cacc[mi][ni][hf * 2 + 1];
                bf16 h0 = __float2bfloat16(v0), h1 = __float2bfloat16(v1);
                bf16 l0 = __float2bfloat16(v0 - __bfloat162float(h0));
                bf16 l1 = __float2bfloat16(v1 - __bfloat162float(h1));
                size_t off = (size_t)row * 512 + col;
                *(bf162*)&g_ch[off] = bf162(h0, h1);
                *(bf162*)&g_cl[off] = bf162(l0, l1);
            }
}

// ---------------------------------------------------------------------------
extern "C" void kernel_launch(void* const* d_in, const int* in_sizes, int n_in,
                              void* d_out, int out_size)
{
    const float* x  = (const float*)d_in[0];
    const float* W[4] = {(const float*)d_in[1], (const float*)d_in[2],
                         (const float*)d_in[3], (const float*)d_in[4]};
    float* out = (float*)d_out;

    bf16 *xh, *xl, *wh, *wl, *qh, *ql, *kh, *kl, *ch, *cl;
    __half* vf;
    cudaGetSymbolAddress((void**)&xh, g_xh);
    cudaGetSymbolAddress((void**)&xl, g_xl);
    cudaGetSymbolAddress((void**)&wh, g_wh);
    cudaGetSymbolAddress((void**)&wl, g_wl);
    cudaGetSymbolAddress((void**)&qh, g_qh);
    cudaGetSymbolAddress((void**)&ql, g_ql);
    cudaGetSymbolAddress((void**)&kh, g_kh);
    cudaGetSymbolAddress((void**)&kl, g_kl);
    cudaGetSymbolAddress((void**)&vf, g_vf);
    cudaGetSymbolAddress((void**)&ch, g_ch);
    cudaGetSymbolAddress((void**)&cl, g_cl);

    // splits
    split_kernel<<<(M_ * D_) / 256, 256>>>(x, xh, xl, M_ * D_);
    for (int i = 0; i < 4; i++)
        split_kernel<<<(D_ * D_) / 256, 256>>>(W[i], wh + (size_t)i * D_ * D_,
                                               wl + (size_t)i * D_ * D_, D_ * D_);

    dim3 gp(D_ / 64, M_ / 128);   // (8, 64)
    gemm_proj<<<gp, 256>>>(xh, xl, wh, wl, qh, ql, nullptr, nullptr, 0);
    gemm_proj<<<gp, 256>>>(xh, xl, wh + (size_t)1 * D_ * D_, wl + (size_t)1 * D_ * D_,
                           kh, kl, nullptr, nullptr, 0);
    gemm_proj<<<gp, 256>>>(xh, xl, wh + (size_t)2 * D_ * D_, wl + (size_t)2 * D_ * D_,
                           nullptr, nullptr, nullptr, vf, 2);

    cudaFuncSetAttribute(fused_attn, cudaFuncAttributeMaxDynamicSharedMemorySize,
                         225792);
    dim3 ga(S_ / 64, B_);         // (64, 2) = 128 CTAs, one full wave
    fused_attn<<<ga, 512, 225792>>>(qh, ql, kh, kl, vf);

    gemm_proj<<<gp, 256>>>(ch, cl, wh + (size_t)3 * D_ * D_, wl + (size_t)3 * D_ * D_,
                           nullptr, nullptr, out, nullptr, 1);
}

// round 6
// speedup vs baseline: 3.3865x; 1.2436x over previous
#include <cuda_runtime.h>
#include <cuda_bf16.h>
#include <cuda_fp16.h>

typedef __nv_bfloat16 bf16;
typedef __nv_bfloat162 bf162;

#define B_ 2
#define S_ 4096
#define D_ 512
#define M_ (B_ * S_)

// ---------------- scratch ----------------
__device__ bf16 g_xh[(size_t)M_ * D_];
__device__ bf16 g_xl[(size_t)M_ * D_];
__device__ bf16 g_wh[4][D_ * D_];
__device__ bf16 g_wl[4][D_ * D_];
__device__ __half g_qf[(size_t)M_ * D_];
__device__ __half g_kf[(size_t)M_ * D_];
__device__ __half g_vf[(size_t)M_ * D_];
__device__ bf16 g_ch[(size_t)M_ * D_];
__device__ bf16 g_cl[(size_t)M_ * D_];

// ---------------- ptx helpers ----------------
__device__ __forceinline__ unsigned smaddr(const void* p) {
    return (unsigned)__cvta_generic_to_shared(p);
}
__device__ __forceinline__ void ldsm4(unsigned* r, unsigned a) {
    asm volatile("ldmatrix.sync.aligned.m8n8.x4.shared.b16 {%0,%1,%2,%3},[%4];"
                 : "=r"(r[0]), "=r"(r[1]), "=r"(r[2]), "=r"(r[3]) : "r"(a));
}
__device__ __forceinline__ void ldsm2(unsigned* r, unsigned a) {
    asm volatile("ldmatrix.sync.aligned.m8n8.x2.shared.b16 {%0,%1},[%2];"
                 : "=r"(r[0]), "=r"(r[1]) : "r"(a));
}
__device__ __forceinline__ void ldsm2t(unsigned* r, unsigned a) {
    asm volatile("ldmatrix.sync.aligned.m8n8.x2.trans.shared.b16 {%0,%1},[%2];"
                 : "=r"(r[0]), "=r"(r[1]) : "r"(a));
}
__device__ __forceinline__ void mma16816(float* c, const unsigned* a, const unsigned* b) {
    asm volatile(
        "mma.sync.aligned.m16n8k16.row.col.f32.bf16.bf16.f32 "
        "{%0,%1,%2,%3},{%4,%5,%6,%7},{%8,%9},{%0,%1,%2,%3};"
        : "+f"(c[0]), "+f"(c[1]), "+f"(c[2]), "+f"(c[3])
        : "r"(a[0]), "r"(a[1]), "r"(a[2]), "r"(a[3]), "r"(b[0]), "r"(b[1]));
}
__device__ __forceinline__ void mma16816h(float* c, const unsigned* a, const unsigned* b) {
    asm volatile(
        "mma.sync.aligned.m16n8k16.row.col.f32.f16.f16.f32 "
        "{%0,%1,%2,%3},{%4,%5,%6,%7},{%8,%9},{%0,%1,%2,%3};"
        : "+f"(c[0]), "+f"(c[1]), "+f"(c[2]), "+f"(c[3])
        : "r"(a[0]), "r"(a[1]), "r"(a[2]), "r"(a[3]), "r"(b[0]), "r"(b[1]));
}
__device__ __forceinline__ void cpa16(unsigned d, const void* g) {
    asm volatile("cp.async.cg.shared.global [%0], [%1], 16;" :: "r"(d), "l"(g));
}
__device__ __forceinline__ void cpcommit() { asm volatile("cp.async.commit_group;"); }
__device__ __forceinline__ void cpwait0()  { asm volatile("cp.async.wait_group 0;" ::: "memory"); }

// ---------------- split fp32 -> bf16 hi/lo ----------------
__global__ __launch_bounds__(256) void split_kernel(
    const float* __restrict__ in, bf16* __restrict__ hi, bf16* __restrict__ lo, int n)
{
    int i = blockIdx.x * 256 + threadIdx.x;
    if (i < n) {
        float v = in[i];
        bf16 h = __float2bfloat16(v);
        hi[i] = h;
        lo[i] = __float2bfloat16(v - __bfloat162float(h));
    }
}

// ---------------- projection GEMM: C[M,512] = A[M,512] @ W[512,512]^T --------
// 3-term bf16 mma. mode 0: bf16 hi/lo out. mode 1: relu + fp32 out. mode 2: fp16 out.
__global__ __launch_bounds__(256) void gemm_proj(
    const bf16* __restrict__ Ah, const bf16* __restrict__ Al,
    const bf16* __restrict__ Wh, const bf16* __restrict__ Wl,
    bf16* __restrict__ Ch, bf16* __restrict__ Cl,
    float* __restrict__ Cf, __half* __restrict__ Cfh, int mode)
{
    __shared__ bf16 sAh[128 * 40], sAl[128 * 40], sWh[64 * 40], sWl[64 * 40];

    const int tid = threadIdx.x, lane = tid & 31, warp = tid >> 5;
    const int m0 = blockIdx.y * 128, n0 = blockIdx.x * 64;
    const int wm = warp >> 1, wn = warp & 1;

    float acc[2][4][4];
#pragma unroll
    for (int a = 0; a < 2; a++)
#pragma unroll
        for (int b = 0; b < 4; b++)
#pragma unroll
            for (int c = 0; c < 4; c++) acc[a][b][c] = 0.0f;

    for (int k0 = 0; k0 < 512; k0 += 32) {
        __syncthreads();
#pragma unroll
        for (int j = 0; j < 4; j++) {
            int u = tid + j * 256;
            int half = u >> 9, rem = u & 511;
            int row = rem >> 2, c4 = rem & 3;
            const bf16* src = (half ? Al : Ah) + (size_t)(m0 + row) * 512 + k0 + c4 * 8;
            bf16* dst = (half ? sAl : sAh) + row * 40 + c4 * 8;
            *(uint4*)dst = *(const uint4*)src;
        }
#pragma unroll
        for (int j = 0; j < 2; j++) {
            int u = tid + j * 256;
            int half = u >> 8, rem = u & 255;
            int row = rem >> 2, c4 = rem & 3;
            const bf16* src = (half ? Wl : Wh) + (size_t)(n0 + row) * 512 + k0 + c4 * 8;
            bf16* dst = (half ? sWl : sWh) + row * 40 + c4 * 8;
            *(uint4*)dst = *(const uint4*)src;
        }
        __syncthreads();

#pragma unroll
        for (int kc = 0; kc < 2; kc++) {
            unsigned ah[2][4], al[2][4];
#pragma unroll
            for (int mi = 0; mi < 2; mi++) {
                int r = wm * 32 + mi * 16 + (lane & 15);
                int cc = kc * 16 + (lane >> 4) * 8;
                ldsm4(ah[mi], smaddr(&sAh[r * 40 + cc]));
                ldsm4(al[mi], smaddr(&sAl[r * 40 + cc]));
            }
#pragma unroll
            for (int ni = 0; ni < 4; ni++) {
                int r = wn * 32 + ni * 8 + (lane & 7);
                int cc = kc * 16 + ((lane >> 3) & 1) * 8;
                unsigned bh[2], bl[2];
                ldsm2(bh, smaddr(&sWh[r * 40 + cc]));
                ldsm2(bl, smaddr(&sWl[r * 40 + cc]));
#pragma unroll
                for (int mi = 0; mi < 2; mi++) {
                    mma16816(acc[mi][ni], ah[mi], bh);
                    mma16816(acc[mi][ni], ah[mi], bl);
                    mma16816(acc[mi][ni], al[mi], bh);
                }
            }
        }
    }

#pragma unroll
    for (int mi = 0; mi < 2; mi++)
#pragma unroll
        for (int ni = 0; ni < 4; ni++) {
#pragma unroll
            for (int half = 0; half < 2; half++) {
                int row = m0 + wm * 32 + mi * 16 + (lane >> 2) + half * 8;
                int col = n0 + wn * 32 + ni * 8 + (lane & 3) * 2;
                float v0 = acc[mi][ni][half * 2 + 0];
                float v1 = acc[mi][ni][half * 2 + 1];
                size_t off = (size_t)row * 512 + col;
                if (mode == 1) {
                    *(float2*)&Cf[off] = make_float2(fmaxf(v0, 0.f), fmaxf(v1, 0.f));
                } else if (mode == 2) {
                    *(__half2*)&Cfh[off] = __floats2half2_rn(v0, v1);
                } else {
                    bf16 h0 = __float2bfloat16(v0), h1 = __float2bfloat16(v1);
                    bf16 l0 = __float2bfloat16(v0 - __bfloat162float(h0));
                    bf16 l1 = __float2bfloat16(v1 - __bfloat162float(h1));
                    *(bf162*)&Ch[off] = bf162(h0, h1);
                    *(bf162*)&Cl[off] = bf162(l0, l1);
                }
            }
        }
}

// ---------------- fused attention -----------------------------------------
// CTA: 64 q rows x all heads, 512 threads. warp = (head, q-half of 32 rows).
// All fp16 single: scores 1 mma per frag pair, PV 1 mma.
// heads-softmax with exact rintf(-1e9) emulation on the masked path.
#define QSTR 520
#define KVELEM 16640        // elems per KV buffer (K fp16 + V fp16, 16x520 each)
#define SCH 1088            // floats per head in ssc (64*17)
#define ATH 1536            // halfs per head in sat (64*24)

__global__ __launch_bounds__(512, 1) void fused_attn(
    const __half* __restrict__ qfp, const __half* __restrict__ kfp,
    const __half* __restrict__ vfp)
{
    extern __shared__ char smem[];
    __half* kv = (__half*)smem;                    // 2 x 16640 elems = 66560 B
    float* ssc = (float*)(smem + 66560);           // 8 x 1088 fp32 = 34816 B
    __half* sat = (__half*)(smem + 101376);        // 8 x 1536 fp16 = 24576 B

    const int tid = threadIdx.x, lane = tid & 31, w = tid >> 5;
    const int h = w & 7, qhalf = w >> 3;
    const int qt = blockIdx.x, b = blockIdx.y;
    const size_t kvbase = (size_t)b * S_ * D_;
    const int qg0 = qt * 64;

    // ---- stage Q (64x512 fp16, stride 520) into kv area (transient) ----
#pragma unroll
    for (int j = 0; j < 8; j++) {
        int u = tid + j * 512;                 // 0..4095
        int row = u >> 6, cc = u & 63;
        const __half* src = qfp + (size_t)(b * S_ + qg0 + row) * 512 + cc * 8;
        *(uint4*)&kv[row * QSTR + cc * 8] = *(const uint4*)src;
    }
    __syncthreads();

    unsigned qf[2][4][4];
#pragma unroll
    for (int mi = 0; mi < 2; mi++)
#pragma unroll
        for (int dc = 0; dc < 4; dc++) {
            int row = qhalf * 32 + mi * 16 + (lane & 15);
            int col = h * 64 + dc * 16 + (lane >> 4) * 8;
            ldsm4(qf[mi][dc], smaddr(&kv[row * QSTR + col]));
        }
    __syncthreads();    // kv area free for KV streaming

    float cacc[2][8][4];
#pragma unroll
    for (int mi = 0; mi < 2; mi++)
#pragma unroll
        for (int ni = 0; ni < 8; ni++)
#pragma unroll
            for (int c = 0; c < 4; c++) cacc[mi][ni][c] = 0.0f;

    // ---- prefetch iter 0: 2 arrays x 16 rows x 64 chunks = 2048 ----
#pragma unroll
    for (int j = 0; j < 4; j++) {
        int c = tid + j * 512;
        int arr = c >> 10, rem = c & 1023;
        int r = rem >> 6, cc = rem & 63;
        size_t goff = kvbase + (size_t)r * 512 + cc * 8;
        const __half* src = (arr == 0) ? (kfp + goff) : (vfp + goff);
        cpa16(smaddr(kv + arr * 8320 + r * 520 + cc * 8), src);
    }
    cpcommit();

    for (int it = 0; it < 256; it++) {
        __half* buf = kv + (it & 1) * KVELEM;
        const __half* Kf = buf;
        const __half* Vf = buf + 8320;

        cpwait0();
        __syncthreads();

        if (it + 1 < 256) {
            __half* nb = kv + ((it + 1) & 1) * KVELEM;
            const size_t rowoff = kvbase + (size_t)(it + 1) * 16 * 512;
#pragma unroll
            for (int j = 0; j < 4; j++) {
                int c = tid + j * 512;
                int arr = c >> 10, rem = c & 1023;
                int r = rem >> 6, cc = rem & 63;
                size_t goff = rowoff + (size_t)r * 512 + cc * 8;
                const __half* src = (arr == 0) ? (kfp + goff) : (vfp + goff);
                cpa16(smaddr(nb + arr * 8320 + r * 520 + cc * 8), src);
            }
            cpcommit();
        }

        // ---- scores: 32q x 16k for (head h, qhalf), single fp16 mma ----
        float cs[2][2][4];
#pragma unroll
        for (int mi = 0; mi < 2; mi++)
#pragma unroll
            for (int ni = 0; ni < 2; ni++)
#pragma unroll
                for (int c = 0; c < 4; c++) cs[mi][ni][c] = 0.0f;

#pragma unroll
        for (int dc = 0; dc < 4; dc++) {
            unsigned k2[2][2];
#pragma unroll
            for (int ni = 0; ni < 2; ni++) {
                int kr = ni * 8 + (lane & 7);
                int col = h * 64 + dc * 16 + ((lane >> 3) & 1) * 8;
                ldsm2(k2[ni], smaddr(&Kf[kr * 520 + col]));
            }
#pragma unroll
            for (int mi = 0; mi < 2; mi++)
#pragma unroll
                for (int ni = 0; ni < 2; ni++)
                    mma16816h(cs[mi][ni], qf[mi][dc], k2[ni]);
        }
#pragma unroll
        for (int mi = 0; mi < 2; mi++)
#pragma unroll
            for (int ni = 0; ni < 2; ni++) {
                int row = qhalf * 32 + mi * 16 + (lane >> 2);
                int col = ni * 8 + (lane & 3) * 2;
                float* p0 = &ssc[h * SCH + row * 17 + col];
                p0[0] = cs[mi][ni][0]; p0[1] = cs[mi][ni][1];
                float* p1 = &ssc[h * SCH + (row + 8) * 17 + col];
                p1[0] = cs[mi][ni][2]; p1[1] = cs[mi][ni][3];
            }
        __syncthreads();

        // ---- heads softmax: 1024 (q,k) pairs, 2 per thread ----
#pragma unroll
        for (int rep = 0; rep < 2; rep++) {
            int p = tid + rep * 512;
            int q = p >> 4, kk = p & 15;
            int qg = qg0 + q, kg = it * 16 + kk;
            bool masked = kg > qg;
            float t[8];
#pragma unroll
            for (int hh = 0; hh < 8; hh++) {
                float s = ssc[hh * SCH + q * 17 + kk];
                t[hh] = masked ? 8.0f * rintf(s * 0.015625f) : s * 0.125f;
            }
            float m = t[0];
#pragma unroll
            for (int hh = 1; hh < 8; hh++) m = fmaxf(m, t[hh]);
            float e[8], sum = 0.0f;
#pragma unroll
            for (int hh = 0; hh < 8; hh++) { e[hh] = __expf(t[hh] - m); sum += e[hh]; }
            float inv = 1.0f / sum;
#pragma unroll
            for (int hh = 0; hh < 8; hh++)
                sat[hh * ATH + q * 24 + kk] = __float2half_rn(e[hh] * inv);
        }
        __syncthreads();

        // ---- PV: single fp16 mma ----
        unsigned af[2][4];
#pragma unroll
        for (int mi = 0; mi < 2; mi++) {
            int row = qhalf * 32 + mi * 16 + (lane & 15);
            ldsm4(af[mi], smaddr(&sat[h * ATH + row * 24 + (lane >> 4) * 8]));
        }
#pragma unroll
        for (int ni = 0; ni < 8; ni++) {
            unsigned v2[2];
            ldsm2t(v2, smaddr(&Vf[(lane & 15) * 520 + h * 64 + ni * 8]));
#pragma unroll
            for (int mi = 0; mi < 2; mi++)
                mma16816h(cacc[mi][ni], af[mi], v2);
        }
    }

    // ---- epilogue: ctx -> bf16 hi/lo ----
#pragma unroll
    for (int mi = 0; mi < 2; mi++)
#pragma unroll
        for (int ni = 0; ni < 8; ni++)
#pragma unroll
            for (int hf = 0; hf < 2; hf++) {
                int row = b * S_ + qg0 + qhalf * 32 + mi * 16 + (lane >> 2) + hf * 8;
                int col = h * 64 + ni * 8 + (lane & 3) * 2;
                float v0 = cacc[mi][ni][hf * 2 + 0];
                float v1 = cacc[mi][ni][hf * 2 + 1];
                bf16 h0 = __float2bfloat16(v0), h1 = __float2bfloat16(v1);
                bf16 l0 = __float2bfloat16(v0 - __bfloat162float(h0));
                bf16 l1 = __float2bfloat16(v1 - __bfloat162float(h1));
                size_t off = (size_t)row * 512 + col;
                *(bf162*)&g_ch[off] = bf162(h0, h1);
                *(bf162*)&g_cl[off] = bf162(l0, l1);
            }
}

// ---------------------------------------------------------------------------
extern "C" void kernel_launch(void* const* d_in, const int* in_sizes, int n_in,
                              void* d_out, int out_size)
{
    const float* x  = (const float*)d_in[0];
    const float* W[4] = {(const float*)d_in[1], (const float*)d_in[2],
                         (const float*)d_in[3], (const float*)d_in[4]};
    float* out = (float*)d_out;

    bf16 *xh, *xl, *wh, *wl, *ch, *cl;
    __half *qf, *kf, *vf;
    cudaGetSymbolAddress((void**)&xh, g_xh);
    cudaGetSymbolAddress((void**)&xl, g_xl);
    cudaGetSymbolAddress((void**)&wh, g_wh);
    cudaGetSymbolAddress((void**)&wl, g_wl);
    cudaGetSymbolAddress((void**)&qf, g_qf);
    cudaGetSymbolAddress((void**)&kf, g_kf);
    cudaGetSymbolAddress((void**)&vf, g_vf);
    cudaGetSymbolAddress((void**)&ch, g_ch);
    cudaGetSymbolAddress((void**)&cl, g_cl);

    // splits
    split_kernel<<<(M_ * D_) / 256, 256>>>(x, xh, xl, M_ * D_);
    for (int i = 0; i < 4; i++)
        split_kernel<<<(D_ * D_) / 256, 256>>>(W[i], wh + (size_t)i * D_ * D_,
                                               wl + (size_t)i * D_ * D_, D_ * D_);

    dim3 gp(D_ / 64, M_ / 128);   // (8, 64)
    gemm_proj<<<gp, 256>>>(xh, xl, wh, wl, nullptr, nullptr, nullptr, qf, 2);
    gemm_proj<<<gp, 256>>>(xh, xl, wh + (size_t)1 * D_ * D_, wl + (size_t)1 * D_ * D_,
                           nullptr, nullptr, nullptr, kf, 2);
    gemm_proj<<<gp, 256>>>(xh, xl, wh + (size_t)2 * D_ * D_, wl + (size_t)2 * D_ * D_,
                           nullptr, nullptr, nullptr, vf, 2);

    cudaFuncSetAttribute(fused_attn, cudaFuncAttributeMaxDynamicSharedMemorySize,
                         125952);
    dim3 ga(S_ / 64, B_);         // (64, 2) = 128 CTAs, one full wave
    fused_attn<<<ga, 512, 125952>>>(qf, kf, vf);

    gemm_proj<<<gp, 256>>>(ch, cl, wh + (size_t)3 * D_ * D_, wl + (size_t)3 * D_ * D_,
                           nullptr, nullptr, out, nullptr, 1);
}